// round 3
// baseline (speedup 1.0000x reference)
#include <cuda_runtime.h>
#include <math.h>

// Problem constants
#define BD 4
#define ND 2048
#define CD 256
#define INNER 1024
#define ROWS (BD*ND)          // 8192
#define EPS 1e-5f
#define ATT_SCALE 0.125f      // 64^-0.5

// ---------------- scratch (device globals; allocation-free rule) -------------
__device__ float g_qn[ROWS*CD];
__device__ float g_kn[ROWS*CD];
__device__ float g_vn[ROWS*CD];
__device__ float g_qp[ROWS*INNER];
__device__ float g_kp[ROWS*INNER];
__device__ float g_vp[ROWS*INNER];
__device__ float g_attn[(long long)BD*ND*ND];   // 64 MB
__device__ float g_x[ROWS*INNER];
// tf32-rounded weights
__device__ float g_wq[CD*INNER];
__device__ float g_wk[CD*INNER];
__device__ float g_wv[CD*INNER];
__device__ float g_wo[INNER*CD];

// ---------------- helpers ----------------
__device__ __forceinline__ float warp_sum(float v) {
    #pragma unroll
    for (int o = 16; o; o >>= 1) v += __shfl_xor_sync(0xffffffffu, v, o);
    return v;
}
__device__ __forceinline__ float warp_max(float v) {
    #pragma unroll
    for (int o = 16; o; o >>= 1) v = fmaxf(v, __shfl_xor_sync(0xffffffffu, v, o));
    return v;
}
__device__ __forceinline__ float block_sum256(float v, float* shm) {
    v = warp_sum(v);
    int w = threadIdx.x >> 5;
    if ((threadIdx.x & 31) == 0) shm[w] = v;
    __syncthreads();
    if (threadIdx.x == 0) {
        float s = 0.f;
        #pragma unroll
        for (int i = 0; i < 8; i++) s += shm[i];
        shm[8] = s;
    }
    __syncthreads();
    float r = shm[8];
    __syncthreads();
    return r;
}
__device__ __forceinline__ float block_max256(float v, float* shm) {
    v = warp_max(v);
    int w = threadIdx.x >> 5;
    if ((threadIdx.x & 31) == 0) shm[w] = v;
    __syncthreads();
    if (threadIdx.x == 0) {
        float m = shm[0];
        #pragma unroll
        for (int i = 1; i < 8; i++) m = fmaxf(m, shm[i]);
        shm[8] = m;
    }
    __syncthreads();
    float r = shm[8];
    __syncthreads();
    return r;
}

__device__ __forceinline__ float f2tf(float f) {
    unsigned r;
    asm("cvt.rna.tf32.f32 %0, %1;" : "=r"(r) : "f"(f));
    return __uint_as_float(r);
}

__device__ __forceinline__ void mma_tf32(float* c, const unsigned* a, const unsigned* b) {
    asm volatile(
        "mma.sync.aligned.m16n8k8.row.col.f32.tf32.tf32.f32 "
        "{%0,%1,%2,%3}, {%4,%5,%6,%7}, {%8,%9}, {%0,%1,%2,%3};"
        : "+f"(c[0]), "+f"(c[1]), "+f"(c[2]), "+f"(c[3])
        : "r"(a[0]), "r"(a[1]), "r"(a[2]), "r"(a[3]), "r"(b[0]), "r"(b[1]));
}

__device__ __forceinline__ void cp16(float* smem_dst, const float* gmem_src) {
    unsigned s = (unsigned)__cvta_generic_to_shared(smem_dst);
    asm volatile("cp.async.cg.shared.global [%0], [%1], 16;" :: "r"(s), "l"(gmem_src));
}
__device__ __forceinline__ void cp_commit() {
    asm volatile("cp.async.commit_group;");
}
template<int NN>
__device__ __forceinline__ void cp_wait() {
    asm volatile("cp.async.wait_group %0;" :: "n"(NN));
}

// ---------------- weight tf32 pre-round -------------------------------------
__global__ void cvt_kernel(const float* __restrict__ src, float* __restrict__ dst, int n4) {
    int i = blockIdx.x * 256 + threadIdx.x;
    if (i < n4) {
        float4 v = reinterpret_cast<const float4*>(src)[i];
        v.x = f2tf(v.x); v.y = f2tf(v.y); v.z = f2tf(v.z); v.w = f2tf(v.w);
        reinterpret_cast<float4*>(dst)[i] = v;
    }
}

// ---------------- LayerNorm (writes tf32-rounded) ---------------------------
__global__ void ln_kernel(const float* __restrict__ q, const float* __restrict__ k,
                          const float* __restrict__ v, const float* __restrict__ g,
                          const float* __restrict__ b) {
    __shared__ float shm[9];
    const float* src;
    float* dst;
    int which = blockIdx.y;
    long long off = (long long)blockIdx.x * CD;
    if (which == 0)      { src = q + off; dst = g_qn + off; }
    else if (which == 1) { src = k + off; dst = g_kn + off; }
    else                 { src = v + off; dst = g_vn + off; }

    int t = threadIdx.x;
    float x = src[t];
    float mean = block_sum256(x, shm) * (1.0f / CD);
    float d = x - mean;
    float var = block_sum256(d * d, shm) * (1.0f / CD);
    float inv = rsqrtf(var + EPS);
    dst[t] = f2tf(d * inv * g[t] + b[t]);
}

// ---------------- pipelined tf32 tensor-core GEMM ---------------------------
// C = alpha * A @ B(^T) (+ bias).  A: [M,K] row-major, values already tf32.
// !TRANS_B: B is [K,N].  TRANS_B: B is [N,K] (compute A @ B^T).
// Block tile 128x128x32, 8 warps (4Mx2N), warp tile 32x64, mma m16n8k8.
// 2-stage cp.async double buffer, dynamic smem.
template<bool TRANS_B, bool HAS_BIAS, bool ROUND_OUT>
__global__ __launch_bounds__(256)
void mma_gemm(const float* __restrict__ A, const float* __restrict__ B,
              const float* __restrict__ bias, float* __restrict__ Cout,
              int M, int N, int K, float alpha,
              long long strideA, long long strideB, long long strideC) {
    constexpr int BM = 128, BN = 128, BK = 32;
    constexpr int AS = 36;                  // As row stride
    constexpr int BS = TRANS_B ? 36 : 136;  // Bs row stride (conflict-free both)
    constexpr int ASZ = BM * AS;            // 4608 floats
    constexpr int BSZ = TRANS_B ? BN * 36 : BK * 136;

    extern __shared__ float smem[];
    float* As_[2] = { smem, smem + ASZ };
    float* Bs_[2] = { smem + 2 * ASZ, smem + 2 * ASZ + BSZ };

    A    += (long long)blockIdx.z * strideA;
    B    += (long long)blockIdx.z * strideB;
    Cout += (long long)blockIdx.z * strideC;

    const int tid  = threadIdx.x;
    const int lane = tid & 31;
    const int w    = tid >> 5;
    const int g    = lane >> 2;
    const int tg   = lane & 3;
    const int warpM = (w >> 1) * 32;
    const int warpN = (w & 1) * 64;
    const long long bm = (long long)blockIdx.y * BM;
    const long long bn = (long long)blockIdx.x * BN;

    const int ar = tid >> 3;               // 0..31
    const int ac = (tid & 7) * 4;          // 0..28

    float acc[2][8][4];
    #pragma unroll
    for (int i = 0; i < 2; i++)
        #pragma unroll
        for (int j = 0; j < 8; j++)
            #pragma unroll
            for (int q_ = 0; q_ < 4; q_++) acc[i][j][q_] = 0.f;

    auto fill = [&](int st, int k0) {
        float* as = As_[st];
        float* bs = Bs_[st];
        #pragma unroll
        for (int i = 0; i < 4; i++) {
            int r = ar + i * 32;
            cp16(&as[r * AS + ac], A + (bm + r) * K + k0 + ac);
        }
        if (TRANS_B) {
            #pragma unroll
            for (int i = 0; i < 4; i++) {
                int r = ar + i * 32;
                cp16(&bs[r * BS + ac], B + (bn + r) * K + k0 + ac);
            }
        } else {
            #pragma unroll
            for (int i = 0; i < 4; i++) {
                int kk = (tid >> 5) + i * 8;
                int c  = (tid & 31) * 4;
                cp16(&bs[kk * BS + c], B + (long long)(k0 + kk) * N + bn + c);
            }
        }
    };

    const int nit = K / BK;
    fill(0, 0);
    cp_commit();

    for (int it = 0; it < nit; it++) {
        if (it + 1 < nit) {
            fill((it + 1) & 1, (it + 1) * BK);
            cp_commit();
            cp_wait<1>();
        } else {
            cp_wait<0>();
        }
        __syncthreads();

        const float* as = As_[it & 1];
        const float* bs = Bs_[it & 1];

        #pragma unroll
        for (int ks = 0; ks < 4; ks++) {
            const int kb = ks * 8;
            unsigned af[2][4];
            #pragma unroll
            for (int mt = 0; mt < 2; mt++) {
                int m = warpM + mt * 16;
                af[mt][0] = __float_as_uint(as[(m + g)     * AS + kb + tg]);
                af[mt][1] = __float_as_uint(as[(m + g + 8) * AS + kb + tg]);
                af[mt][2] = __float_as_uint(as[(m + g)     * AS + kb + tg + 4]);
                af[mt][3] = __float_as_uint(as[(m + g + 8) * AS + kb + tg + 4]);
            }
            unsigned bf[8][2];
            #pragma unroll
            for (int nt = 0; nt < 8; nt++) {
                int n = warpN + nt * 8 + g;
                if (TRANS_B) {
                    bf[nt][0] = __float_as_uint(bs[n * BS + kb + tg]);
                    bf[nt][1] = __float_as_uint(bs[n * BS + kb + tg + 4]);
                } else {
                    bf[nt][0] = __float_as_uint(bs[(kb + tg)     * BS + n]);
                    bf[nt][1] = __float_as_uint(bs[(kb + tg + 4) * BS + n]);
                }
            }
            #pragma unroll
            for (int mt = 0; mt < 2; mt++)
                #pragma unroll
                for (int nt = 0; nt < 8; nt++)
                    mma_tf32(acc[mt][nt], af[mt], bf[nt]);
        }
        __syncthreads();
    }

    // ---- epilogue ----
    #pragma unroll
    for (int mt = 0; mt < 2; mt++) {
        #pragma unroll
        for (int nt = 0; nt < 8; nt++) {
            long long row0 = bm + warpM + mt * 16 + g;
            long long col  = bn + warpN + nt * 8 + tg * 2;
            float b0 = 0.f, b1 = 0.f;
            if (HAS_BIAS) { b0 = bias[col]; b1 = bias[col + 1]; }
            float o00 = acc[mt][nt][0] * alpha + b0;
            float o01 = acc[mt][nt][1] * alpha + b1;
            float o10 = acc[mt][nt][2] * alpha + b0;
            float o11 = acc[mt][nt][3] * alpha + b1;
            if (ROUND_OUT) {
                o00 = f2tf(o00); o01 = f2tf(o01); o10 = f2tf(o10); o11 = f2tf(o11);
            }
            *reinterpret_cast<float2*>(Cout + row0 * N + col)       = make_float2(o00, o01);
            *reinterpret_cast<float2*>(Cout + (row0 + 8) * N + col) = make_float2(o10, o11);
        }
    }
}

// ---------------- softmax over rows of g_attn (len 2048), writes tf32 -------
__global__ void softmax_kernel() {
    __shared__ float shm[9];
    float* row = g_attn + (long long)blockIdx.x * ND;
    int t = threadIdx.x;
    float vals[8];
    float m = -INFINITY;
    #pragma unroll
    for (int i = 0; i < 8; i++) {
        vals[i] = row[t + i * 256];
        m = fmaxf(m, vals[i]);
    }
    m = block_max256(m, shm);
    float s = 0.f;
    #pragma unroll
    for (int i = 0; i < 8; i++) {
        vals[i] = __expf(vals[i] - m);
        s += vals[i];
    }
    s = block_sum256(s, shm);
    float inv = 1.0f / s;
    #pragma unroll
    for (int i = 0; i < 8; i++) row[t + i * 256] = f2tf(vals[i] * inv);
}

// ---------------- launch ----------------------------------------------------
extern "C" void kernel_launch(void* const* d_in, const int* in_sizes, int n_in,
                              void* d_out, int out_size) {
    const float* q    = (const float*)d_in[0];
    const float* k    = (const float*)d_in[1];
    const float* v    = (const float*)d_in[2];
    const float* ln_g = (const float*)d_in[3];
    const float* ln_b = (const float*)d_in[4];
    const float* Wq   = (const float*)d_in[5];
    const float* bq   = (const float*)d_in[6];
    const float* Wk   = (const float*)d_in[7];
    const float* bk   = (const float*)d_in[8];
    const float* Wv   = (const float*)d_in[9];
    const float* bv   = (const float*)d_in[10];
    const float* Wo   = (const float*)d_in[11];
    const float* bo   = (const float*)d_in[12];
    float* out = (float*)d_out;

    float *qn, *kn, *vn, *qp, *kp, *vp, *attn, *x, *wq, *wk, *wv, *wo;
    cudaGetSymbolAddress((void**)&qn, g_qn);
    cudaGetSymbolAddress((void**)&kn, g_kn);
    cudaGetSymbolAddress((void**)&vn, g_vn);
    cudaGetSymbolAddress((void**)&qp, g_qp);
    cudaGetSymbolAddress((void**)&kp, g_kp);
    cudaGetSymbolAddress((void**)&vp, g_vp);
    cudaGetSymbolAddress((void**)&attn, g_attn);
    cudaGetSymbolAddress((void**)&x, g_x);
    cudaGetSymbolAddress((void**)&wq, g_wq);
    cudaGetSymbolAddress((void**)&wk, g_wk);
    cudaGetSymbolAddress((void**)&wv, g_wv);
    cudaGetSymbolAddress((void**)&wo, g_wo);

    // dynamic smem sizes per instantiation
    const int ASZ = 128 * 36;
    const int smem_nt = (2 * ASZ + 2 * 128 * 36) * 4;   // TRANS_B
    const int smem_nn = (2 * ASZ + 2 * 32 * 136) * 4;   // !TRANS_B

    cudaFuncSetAttribute(mma_gemm<false, true,  true >, cudaFuncAttributeMaxDynamicSharedMemorySize, smem_nn);
    cudaFuncSetAttribute(mma_gemm<true,  false, false>, cudaFuncAttributeMaxDynamicSharedMemorySize, smem_nt);
    cudaFuncSetAttribute(mma_gemm<false, false, true >, cudaFuncAttributeMaxDynamicSharedMemorySize, smem_nn);
    cudaFuncSetAttribute(mma_gemm<false, true,  false>, cudaFuncAttributeMaxDynamicSharedMemorySize, smem_nn);

    // 0. pre-round weights to tf32
    cvt_kernel<<<(CD * INNER / 4 + 255) / 256, 256>>>(Wq, wq, CD * INNER / 4);
    cvt_kernel<<<(CD * INNER / 4 + 255) / 256, 256>>>(Wk, wk, CD * INNER / 4);
    cvt_kernel<<<(CD * INNER / 4 + 255) / 256, 256>>>(Wv, wv, CD * INNER / 4);
    cvt_kernel<<<(INNER * CD / 4 + 255) / 256, 256>>>(Wo, wo, INNER * CD / 4);

    // 1. LayerNorm q,k,v (tf32-rounded out)
    ln_kernel<<<dim3(ROWS, 3), 256>>>(q, k, v, ln_g, ln_b);

    // 2. Projections: [8192,256] @ [256,1024] + bias  (tf32-rounded out)
    {
        dim3 grid(INNER / 128, ROWS / 128, 1);
        mma_gemm<false, true, true><<<grid, 256, smem_nn>>>(qn, wq, bq, qp, ROWS, INNER, CD, 1.0f, 0, 0, 0);
        mma_gemm<false, true, true><<<grid, 256, smem_nn>>>(kn, wk, bk, kp, ROWS, INNER, CD, 1.0f, 0, 0, 0);
        mma_gemm<false, true, true><<<grid, 256, smem_nn>>>(vn, wv, bv, vp, ROWS, INNER, CD, 1.0f, 0, 0, 0);
    }

    // 3. Scores: per batch [2048,1024] @ [2048,1024]^T * SCALE
    {
        dim3 grid(ND / 128, ND / 128, BD);
        mma_gemm<true, false, false><<<grid, 256, smem_nt>>>(
            qp, kp, nullptr, attn, ND, ND, INNER, ATT_SCALE,
            (long long)ND * INNER, (long long)ND * INNER, (long long)ND * ND);
    }

    // 4. Softmax rows (tf32-rounded out)
    softmax_kernel<<<BD * ND, 256>>>();

    // 5. AV: per batch [2048,2048] @ [2048,1024]  (tf32-rounded out)
    {
        dim3 grid(INNER / 128, ND / 128, BD);
        mma_gemm<false, false, true><<<grid, 256, smem_nn>>>(
            attn, vp, nullptr, x, ND, INNER, ND, 1.0f,
            (long long)ND * ND, (long long)ND * INNER, (long long)ND * INNER);
    }

    // 6. Output projection: [8192,1024] @ [1024,256] + bias (fp32 out)
    {
        dim3 grid(CD / 128, ROWS / 128, 1);
        mma_gemm<false, true, false><<<grid, 256, smem_nn>>>(x, wo, bo, out, ROWS, CD, INNER, 1.0f, 0, 0, 0);
    }
}